// round 17
// baseline (speedup 1.0000x reference)
#include <cuda_runtime.h>
#include <cuda_bf16.h>
#include <cstdint>

#define NNODES 25000
#define NEDGES 400000
#define FIN 128
#define CW 32
#define WPB 16            // warps per block
#define THREADS 512
#define NTILES 12500      // 32-edge tiles

// persistent scratch (no allocs allowed)
__device__ float g_h[NNODES * CW];
__device__ float g_aggr[NNODES * CW];
__device__ int g_is64;
__device__ int g_tick;     // work-stealing ticket (reset by k_in each launch)

__device__ __forceinline__ float lrelu(float v) {
    return fmaxf(v, 0.f) + 0.01f * fminf(v, 0.f);
}
__device__ __forceinline__ uint32_t bp2(__nv_bfloat16 a, __nv_bfloat16 b) {
    return ((uint32_t)__bfloat16_as_ushort(b) << 16) | __bfloat16_as_ushort(a);
}
__device__ __forceinline__ uint32_t smem_u32(const void* p) {
    uint32_t a;
    asm("{ .reg .u64 t; cvta.to.shared.u64 t,%1; cvt.u32.u64 %0,t; }" : "=r"(a) : "l"(p));
    return a;
}
__device__ __forceinline__ void ldsm4(uint32_t* r, uint32_t addr) {
    asm volatile("ldmatrix.sync.aligned.m8n8.x4.shared.b16 {%0,%1,%2,%3},[%4];"
                 : "=r"(r[0]), "=r"(r[1]), "=r"(r[2]), "=r"(r[3]) : "r"(addr));
}
__device__ __forceinline__ void mma16816(float* d, const uint32_t* a, const uint32_t* b,
                                         float c0, float c1, float c2, float c3) {
    asm volatile("mma.sync.aligned.m16n8k16.row.col.f32.bf16.bf16.f32 "
                 "{%0,%1,%2,%3},{%4,%5,%6,%7},{%8,%9},{%10,%11,%12,%13};"
                 : "=f"(d[0]), "=f"(d[1]), "=f"(d[2]), "=f"(d[3])
                 : "r"(a[0]), "r"(a[1]), "r"(a[2]), "r"(a[3]), "r"(b[0]), "r"(b[1]),
                   "f"(c0), "f"(c1), "f"(c2), "f"(c3));
}
// vector f32x2 global reduction (sm_90+): one transaction per lane for an (o,o+1) pair
__device__ __forceinline__ void red2(float* p, float a, float b) {
    asm volatile("red.global.add.v2.f32 [%0], {%1,%2};" :: "l"(p), "f"(a), "f"(b) : "memory");
}

// k_edge smem layout (bytes)
#define S_W 0                        // W' 1024 rows x 64B ([Wh|Wl]) = 65536
#define S_B 65536                    // bias f32[1024] = 4096
#define S_A 69632                    // A tiles: WPB x 2048B (32 edges x 64B)
#define S_H (S_A + WPB * 2048)       // hT: WPB x 32c x 32e' floats = 4096B/warp
#define S_TOTAL (S_H + WPB * 4096)

// ---- kernel 1: h = lrelu(x @ W_in + b_in); zeros g_aggr; detect dtype; reset ticket ----
#define KIN_T 384
#define KIN_N 48
__global__ void __launch_bounds__(KIN_T) k_in(const void* __restrict__ ei,
                                              const float* __restrict__ x,
                                              const float* __restrict__ Win,
                                              const float* __restrict__ bin) {
    if (blockIdx.x == 0 && threadIdx.x == 0) {
        g_tick = 0;
        const unsigned long long* p = (const unsigned long long*)ei;
        int ok = 1;
        #pragma unroll
        for (int i = 0; i < 16; i++)
            if (p[i] >= (unsigned long long)NNODES) ok = 0;
        g_is64 = ok;  // int32 read as u64 has nonzero high word w.h.p.
    }
    __shared__ float Ws[FIN * CW];    // 16KB
    __shared__ float xs[KIN_N * FIN]; // 24KB
    __shared__ float bs[CW];
    for (int i = threadIdx.x; i < FIN * CW; i += KIN_T) Ws[i] = Win[i];
    if (threadIdx.x < CW) bs[threadIdx.x] = bin[threadIdx.x];
    const int nbase = blockIdx.x * KIN_N;
    for (int i = threadIdx.x; i < KIN_N * (FIN / 4); i += KIN_T) {
        int row = i >> 5, f4 = i & 31;
        int n = nbase + row;
        float4 v = make_float4(0.f, 0.f, 0.f, 0.f);
        if (n < NNODES) v = ((const float4*)(x + (size_t)n * FIN))[f4];
        ((float4*)xs)[i] = v;
    }
    __syncthreads();

    const int wid = threadIdx.x >> 5, lane = threadIdx.x & 31;
    const int r0 = wid * 4;
    float acc0 = bs[lane], acc1 = acc0, acc2 = acc0, acc3 = acc0;
    const float4* x0 = (const float4*)(xs + (r0 + 0) * FIN);
    const float4* x1 = (const float4*)(xs + (r0 + 1) * FIN);
    const float4* x2 = (const float4*)(xs + (r0 + 2) * FIN);
    const float4* x3 = (const float4*)(xs + (r0 + 3) * FIN);
    #pragma unroll 8
    for (int k4 = 0; k4 < FIN / 4; k4++) {
        float4 a = x0[k4], b = x1[k4], c = x2[k4], d = x3[k4];
        float w0 = Ws[(k4 * 4 + 0) * CW + lane];
        float w1 = Ws[(k4 * 4 + 1) * CW + lane];
        float w2 = Ws[(k4 * 4 + 2) * CW + lane];
        float w3 = Ws[(k4 * 4 + 3) * CW + lane];
        acc0 = fmaf(a.x, w0, acc0); acc0 = fmaf(a.y, w1, acc0);
        acc0 = fmaf(a.z, w2, acc0); acc0 = fmaf(a.w, w3, acc0);
        acc1 = fmaf(b.x, w0, acc1); acc1 = fmaf(b.y, w1, acc1);
        acc1 = fmaf(b.z, w2, acc1); acc1 = fmaf(b.w, w3, acc1);
        acc2 = fmaf(c.x, w0, acc2); acc2 = fmaf(c.y, w1, acc2);
        acc2 = fmaf(c.z, w2, acc2); acc2 = fmaf(c.w, w3, acc2);
        acc3 = fmaf(d.x, w0, acc3); acc3 = fmaf(d.y, w1, acc3);
        acc3 = fmaf(d.z, w2, acc3); acc3 = fmaf(d.w, w3, acc3);
    }
    const int n0 = nbase + r0;
    if (n0 + 0 < NNODES) { g_h[(n0 + 0) * CW + lane] = lrelu(acc0); g_aggr[(n0 + 0) * CW + lane] = 0.f; }
    if (n0 + 1 < NNODES) { g_h[(n0 + 1) * CW + lane] = lrelu(acc1); g_aggr[(n0 + 1) * CW + lane] = 0.f; }
    if (n0 + 2 < NNODES) { g_h[(n0 + 2) * CW + lane] = lrelu(acc2); g_aggr[(n0 + 2) * CW + lane] = 0.f; }
    if (n0 + 3 < NNODES) { g_h[(n0 + 3) * CW + lane] = lrelu(acc3); g_aggr[(n0 + 3) * CW + lane] = 0.f; }
}

// ---- kernel 2: HMMA edge stage, 32 edges per warp-tile, work-stealing tickets ----
// Per 8n-chunk: 1 ldsm.x4 B [Wh|Wl] + 1 bias LDS.64 feed 6 MMAs (2 independent
// 3-chains): d = Ah*Wh + bias; d += Al*Wh; d += Ah*Wl.
// h staged transposed hT[c][e'], e'=(e&7)*4+(e>>3) -> one LDS.128 per c-group.
// Epilogue: msg += (0.505h)*d + (0.495h)*|d|. Scatter via red.v2.f32 atomics.
__global__ void __launch_bounds__(THREADS, 1) k_edge(const void* __restrict__ eidx,
                                                     const float* __restrict__ eattr,
                                                     const float* __restrict__ Wedge,
                                                     const float* __restrict__ bedge) {
    extern __shared__ __align__(128) unsigned char sm[];
    const uint32_t smb = smem_u32(sm);
    const int tid = threadIdx.x, lane = tid & 31, warp = tid >> 5;

    // ---- build W' + bias (once per block)
    for (int n = tid; n < 1024; n += THREADS) {
        uint32_t hp8[8], lp8[8];
        #pragma unroll
        for (int q = 0; q < 8; q++) {
            float w0 = Wedge[(2 * q) * 1024 + n];
            float w1 = Wedge[(2 * q + 1) * 1024 + n];
            __nv_bfloat16 h0 = __float2bfloat16(w0);
            __nv_bfloat16 h1 = __float2bfloat16(w1);
            __nv_bfloat16 l0 = __float2bfloat16(w0 - __bfloat162float(h0));
            __nv_bfloat16 l1 = __float2bfloat16(w1 - __bfloat162float(h1));
            hp8[q] = bp2(h0, h1);
            lp8[q] = bp2(l0, l1);
        }
        unsigned char* wr = sm + S_W + n * 64;
        const int sx = (n >> 1) & 3;
        *(uint4*)(wr + ((0 ^ sx) * 16)) = make_uint4(hp8[0], hp8[1], hp8[2], hp8[3]);
        *(uint4*)(wr + ((1 ^ sx) * 16)) = make_uint4(hp8[4], hp8[5], hp8[6], hp8[7]);
        *(uint4*)(wr + ((2 ^ sx) * 16)) = make_uint4(lp8[0], lp8[1], lp8[2], lp8[3]);
        *(uint4*)(wr + ((3 ^ sx) * 16)) = make_uint4(lp8[4], lp8[5], lp8[6], lp8[7]);
        ((float*)(sm + S_B))[n] = bedge[n];
    }
    __syncthreads();

    const int q4 = lane & 3, grp = lane >> 2;
    const uint32_t Aslot = smb + S_A + warp * 2048;
    const int br = lane & 7, bu = lane >> 3;
    const uint32_t bB0 = smb + S_W + br * 64 + ((bu ^ ((br >> 1) & 3)) * 16);
    const int arow = (lane & 7) + 8 * ((lane >> 3) & 1);
    const int au = lane >> 4, asx = (arow >> 1) & 3;
    const uint32_t aaddrh0 = Aslot + arow * 64 + (((0 + au) ^ asx) * 16);
    const uint32_t aaddrl0 = Aslot + arow * 64 + (((2 + au) ^ asx) * 16);
    const float* bias = (const float*)(sm + S_B);
    float* hsl = (float*)(sm + S_H + warp * 4096);  // hT[32c][32e']

    const long long* e64 = (const long long*)eidx;
    const int* e32 = (const int*)eidx;
    const int is64 = g_is64;

    // ---- work-stealing: grab first tile + its edge indices
    int tile;
    if (lane == 0) tile = atomicAdd(&g_tick, 1);
    tile = __shfl_sync(0xFFFFFFFFu, tile, 0);
    int s = 0, dt = 0;
    if (tile < NTILES) {
        const int idx = tile * 32 + lane;
        if (is64) { s = (int)e64[idx]; dt = (int)e64[NEDGES + idx]; }
        else      { s = e32[idx];      dt = e32[NEDGES + idx]; }
    }

    while (tile < NTILES) {
        const int ebase = tile * 32;
        // ---- stage A row (64B = [Ah|Al], swizzled) + transposed h
        {
            const float4* ep = (const float4*)(eattr + (size_t)(ebase + lane) * 16);
            float4 y0 = ep[0], y1 = ep[1], y2 = ep[2], y3 = ep[3];
            float f[16] = {y0.x, y0.y, y0.z, y0.w, y1.x, y1.y, y1.z, y1.w,
                           y2.x, y2.y, y2.z, y2.w, y3.x, y3.y, y3.z, y3.w};
            uint32_t hp[8], lp[8];
            #pragma unroll
            for (int j = 0; j < 8; j++) {
                __nv_bfloat16 h0 = __float2bfloat16(f[2 * j]);
                __nv_bfloat16 h1 = __float2bfloat16(f[2 * j + 1]);
                __nv_bfloat16 l0 = __float2bfloat16(f[2 * j] - __bfloat162float(h0));
                __nv_bfloat16 l1 = __float2bfloat16(f[2 * j + 1] - __bfloat162float(h1));
                hp[j] = bp2(h0, h1);
                lp[j] = bp2(l0, l1);
            }
            unsigned char* ab = sm + S_A + warp * 2048 + lane * 64;
            const int sx = (lane >> 1) & 3;
            *(uint4*)(ab + ((0 ^ sx) * 16)) = make_uint4(hp[0], hp[1], hp[2], hp[3]);
            *(uint4*)(ab + ((1 ^ sx) * 16)) = make_uint4(hp[4], hp[5], hp[6], hp[7]);
            *(uint4*)(ab + ((2 ^ sx) * 16)) = make_uint4(lp[0], lp[1], lp[2], lp[3]);
            *(uint4*)(ab + ((3 ^ sx) * 16)) = make_uint4(lp[4], lp[5], lp[6], lp[7]);
            // h row -> transposed smem: hT[c][e'], e' = (lane&7)*4 + (lane>>3)
            const int e2i = (lane & 7) * 4 + (lane >> 3);
            const float4* hp4 = (const float4*)(g_h + (size_t)s * CW);
            #pragma unroll
            for (int j = 0; j < 8; j++) {
                float4 hv = hp4[j];
                hsl[(4 * j + 0) * 32 + e2i] = hv.x;
                hsl[(4 * j + 1) * 32 + e2i] = hv.y;
                hsl[(4 * j + 2) * 32 + e2i] = hv.z;
                hsl[(4 * j + 3) * 32 + e2i] = hv.w;
            }
        }
        const int dA = __shfl_sync(0xFFFFFFFFu, dt, grp);
        const int dB = __shfl_sync(0xFFFFFFFFu, dt, grp + 8);
        const int dC = __shfl_sync(0xFFFFFFFFu, dt, grp + 16);
        const int dD = __shfl_sync(0xFFFFFFFFu, dt, grp + 24);
        __syncwarp();

        // ---- prefetch next ticket + its edge indices (completes under mainloop)
        int tnext;
        if (lane == 0) tnext = atomicAdd(&g_tick, 1);
        tnext = __shfl_sync(0xFFFFFFFFu, tnext, 0);
        int sn = 0, dn = 0;
        if (tnext < NTILES) {
            const int idx = tnext * 32 + lane;
            if (is64) { sn = (int)e64[idx]; dn = (int)e64[NEDGES + idx]; }
            else      { sn = e32[idx];      dn = e32[NEDGES + idx]; }
        }

        uint32_t aFh0[4], aFl0[4], aFh1[4], aFl1[4];
        ldsm4(aFh0, aaddrh0);
        ldsm4(aFl0, aaddrl0);
        ldsm4(aFh1, aaddrh0 + 1024);
        ldsm4(aFl1, aaddrl0 + 1024);

        float msg[32];
        #pragma unroll
        for (int i = 0; i < 32; i++) msg[i] = 0.f;

        uint32_t bB = bB0;
        const float* bp = bias + 2 * q4;
        float hp0 = 0.f, hm0 = 0.f, hp1 = 0.f, hm1 = 0.f;
        float hp2 = 0.f, hm2 = 0.f, hp3 = 0.f, hm3 = 0.f;
        #pragma unroll 4
        for (int chunk = 0; chunk < 128; chunk++) {
            if ((chunk & 3) == 0) {
                const int c = chunk >> 2;
                // one LDS.128: h[src[grp]][c], h[src[grp+8]][c], h[src[grp+16]][c], h[src[grp+24]][c]
                float4 hv = *(const float4*)(hsl + c * 32 + grp * 4);
                hp0 = 0.505f * hv.x; hm0 = 0.495f * hv.x;
                hp1 = 0.505f * hv.y; hm1 = 0.495f * hv.y;
                hp2 = 0.505f * hv.z; hm2 = 0.495f * hv.z;
                hp3 = 0.505f * hv.w; hm3 = 0.495f * hv.w;
            }
            uint32_t B0[4];
            ldsm4(B0, bB);
            bB += 512;
            float2 bv = *(const float2*)bp;
            bp += 8;
            float d0[4], d1[4];
            mma16816(d0, aFh0, B0 + 0, bv.x, bv.y, bv.x, bv.y);
            mma16816(d1, aFh1, B0 + 0, bv.x, bv.y, bv.x, bv.y);
            mma16816(d0, aFl0, B0 + 0, d0[0], d0[1], d0[2], d0[3]);
            mma16816(d1, aFl1, B0 + 0, d1[0], d1[1], d1[2], d1[3]);
            mma16816(d0, aFh0, B0 + 2, d0[0], d0[1], d0[2], d0[3]);
            mma16816(d1, aFh1, B0 + 2, d1[0], d1[1], d1[2], d1[3]);
            const int p = chunk & 3;
            msg[p * 2 + 0]      = fmaf(hp0, d0[0], fmaf(hm0, fabsf(d0[0]), msg[p * 2 + 0]));
            msg[p * 2 + 1]      = fmaf(hp0, d0[1], fmaf(hm0, fabsf(d0[1]), msg[p * 2 + 1]));
            msg[8 + p * 2 + 0]  = fmaf(hp1, d0[2], fmaf(hm1, fabsf(d0[2]), msg[8 + p * 2 + 0]));
            msg[8 + p * 2 + 1]  = fmaf(hp1, d0[3], fmaf(hm1, fabsf(d0[3]), msg[8 + p * 2 + 1]));
            msg[16 + p * 2 + 0] = fmaf(hp2, d1[0], fmaf(hm2, fabsf(d1[0]), msg[16 + p * 2 + 0]));
            msg[16 + p * 2 + 1] = fmaf(hp2, d1[1], fmaf(hm2, fabsf(d1[1]), msg[16 + p * 2 + 1]));
            msg[24 + p * 2 + 0] = fmaf(hp3, d1[2], fmaf(hm3, fabsf(d1[2]), msg[24 + p * 2 + 0]));
            msg[24 + p * 2 + 1] = fmaf(hp3, d1[3], fmaf(hm3, fabsf(d1[3]), msg[24 + p * 2 + 1]));
        }
        float* aA = g_aggr + (size_t)dA * CW;
        float* aB = g_aggr + (size_t)dB * CW;
        float* aC = g_aggr + (size_t)dC * CW;
        float* aD = g_aggr + (size_t)dD * CW;
        #pragma unroll
        for (int p = 0; p < 4; p++) {
            const int o = p * 8 + 2 * q4;
            red2(aA + o, msg[p * 2], msg[p * 2 + 1]);
            red2(aB + o, msg[8 + p * 2], msg[8 + p * 2 + 1]);
            red2(aC + o, msg[16 + p * 2], msg[16 + p * 2 + 1]);
            red2(aD + o, msg[24 + p * 2], msg[24 + p * 2 + 1]);
        }
        __syncwarp();  // A/h slots reused next tile
        tile = tnext; s = sn; dt = dn;
    }
}

// ---- kernel 3: out = lrelu(aggr + h@W_root + b_conv) @ W_out + b_out ----
__global__ void k_out(const float* __restrict__ Wr, const float* __restrict__ bc,
                      const float* __restrict__ Wo, const float* __restrict__ bo,
                      float* __restrict__ out) {
    __shared__ float Wrs[CW * CW];
    __shared__ float Wos[CW];
    __shared__ float bcs[CW];
    for (int i = threadIdx.x; i < CW * CW; i += blockDim.x) Wrs[i] = Wr[i];
    if (threadIdx.x < CW) { Wos[threadIdx.x] = Wo[threadIdx.x]; bcs[threadIdx.x] = bc[threadIdx.x]; }
    __syncthreads();
    int gw = (blockIdx.x * blockDim.x + threadIdx.x) >> 5;
    int lane = threadIdx.x & 31;
    if (gw >= NNODES) return;
    float r = g_aggr[(size_t)gw * CW + lane] + bcs[lane];
    const float4* hp = (const float4*)(g_h + (size_t)gw * CW);
    #pragma unroll
    for (int c4 = 0; c4 < CW / 4; c4++) {
        float4 h4 = hp[c4];
        int c = c4 * 4;
        r = fmaf(h4.x, Wrs[(c + 0) * CW + lane], r);
        r = fmaf(h4.y, Wrs[(c + 1) * CW + lane], r);
        r = fmaf(h4.z, Wrs[(c + 2) * CW + lane], r);
        r = fmaf(h4.w, Wrs[(c + 3) * CW + lane], r);
    }
    float t = lrelu(r) * Wos[lane];
    #pragma unroll
    for (int off = 16; off; off >>= 1) t += __shfl_xor_sync(0xFFFFFFFFu, t, off);
    if (lane == 0) out[gw] = t + bo[0];
}

extern "C" void kernel_launch(void* const* d_in, const int* in_sizes, int n_in,
                              void* d_out, int out_size) {
    const float* x     = (const float*)d_in[0];
    const void*  ei    = d_in[1];
    const float* ea    = (const float*)d_in[2];
    const float* Win   = (const float*)d_in[3];
    const float* bin   = (const float*)d_in[4];
    const float* Wedge = (const float*)d_in[5];
    const float* bedge = (const float*)d_in[6];
    const float* Wroot = (const float*)d_in[7];
    const float* bconv = (const float*)d_in[8];
    const float* Wout  = (const float*)d_in[9];
    const float* bout  = (const float*)d_in[10];
    float* out = (float*)d_out;

    cudaFuncSetAttribute(k_edge, cudaFuncAttributeMaxDynamicSharedMemorySize, S_TOTAL);

    k_in<<<(NNODES + KIN_N - 1) / KIN_N, KIN_T>>>(ei, x, Win, bin);
    k_edge<<<148, THREADS, S_TOTAL>>>(ei, ea, Wedge, bedge);
    k_out<<<(NNODES * 32 + 255) / 256, 256>>>(Wroot, bconv, Wout, bout, out);
}